// round 1
// baseline (speedup 1.0000x reference)
#include <cuda_runtime.h>

#define BATCH 128
#define TLEN  8192
#define HDIM  96
#define GDIM  384   // 4*H
#define NTHR  416   // 12 gate warps + 1 output warp

// Packed fp32x2 FMA (Blackwell): 2 MACs per issue on the fma pipe.
#define FMA2(d, a, b, c) \
    asm("fma.rn.f32x2 %0, %1, %2, %3;" : "=l"(d) : "l"(a), "l"(b), "l"(c))
#define ADD2(d, a, b) \
    asm("add.rn.f32x2 %0, %1, %2;" : "=l"(d) : "l"(a), "l"(b))
#define UNPACK2(lo, hi, v) \
    asm("mov.b64 {%0, %1}, %2;" : "=f"(lo), "=f"(hi) : "l"(v))

__device__ __forceinline__ float fast_sigmoid(float x) {
    float e = __expf(-x);
    return __fdividef(1.0f, 1.0f + e);
}
__device__ __forceinline__ float fast_tanh(float x) {
    float e = __expf(2.0f * x);
    return 1.0f - __fdividef(2.0f, e + 1.0f);
}

__global__ void __launch_bounds__(NTHR, 1)
lstm_persistent_kernel(const float* __restrict__ x,
                       const float* __restrict__ w_ih,
                       const float* __restrict__ w_hh,
                       const float* __restrict__ b_ih,
                       const float* __restrict__ b_hh,
                       const float* __restrict__ w_out,
                       const float* __restrict__ b_out,
                       float* __restrict__ out)
{
    __shared__ __align__(16) float x_s[TLEN];    // 32 KB: whole input row
    __shared__ __align__(16) float h_s[HDIM];    // current hidden state
    __shared__ __align__(16) float gates_s[GDIM];// activated f,g,o (i stays in reg)

    const int tid = threadIdx.x;
    const int b   = blockIdx.x;
    const int g   = tid;

    // ---- one-time loads ----
    {   // whole x row for this batch element, coalesced float4
        const float4* xg = (const float4*)(x + (size_t)b * TLEN);
        float4* xs = (float4*)x_s;
        for (int i = tid; i < TLEN / 4; i += NTHR) xs[i] = xg[i];
    }
    if (tid < HDIM) h_s[tid] = 0.0f;

    // Per-thread W_hh row (96 fp32 = 24 x ulonglong2) kept in registers.
    ulonglong2 wreg[24];
    float wi = 0.0f, bias = 0.0f;
    if (g < GDIM) {
        const ulonglong2* wr = (const ulonglong2*)(w_hh + (size_t)g * HDIM);
        #pragma unroll
        for (int i = 0; i < 24; i++) wreg[i] = wr[i];
        wi   = w_ih[g];
        bias = b_ih[g] + b_hh[g];
    }

    // Output warp (warp 12) setup
    float wo0 = 0.f, wo1 = 0.f, wo2 = 0.f, bo = 0.f;
    const int lane = tid - GDIM;
    if (g >= GDIM) {
        wo0 = w_out[lane];
        wo1 = w_out[lane + 32];
        wo2 = w_out[lane + 64];
        bo  = b_out[0];
    }

    float c = 0.0f;                              // cell state (update threads)
    float* outrow = out + (size_t)b * TLEN;
    const bool is_update = (g < HDIM);
    const bool is_tanh   = (g >= 192) && (g < 288);
    const ulonglong2* h2 = (const ulonglong2*)h_s;

    __syncthreads();

    for (int t = 0; t < TLEN; t++) {
        float act = 0.0f;
        if (g < GDIM) {
            // ---- phase A: gate matvec (f32x2 packed FMAs, W in regs, h broadcast LDS) ----
            float pre = fmaf(x_s[t], wi, bias);
            unsigned long long a0 = 0ull, a1 = 0ull, a2 = 0ull, a3 = 0ull;
            #pragma unroll
            for (int i = 0; i < 24; i += 2) {
                ulonglong2 hv0 = h2[i];
                FMA2(a0, wreg[i].x,     hv0.x, a0);
                FMA2(a1, wreg[i].y,     hv0.y, a1);
                ulonglong2 hv1 = h2[i + 1];
                FMA2(a2, wreg[i + 1].x, hv1.x, a2);
                FMA2(a3, wreg[i + 1].y, hv1.y, a3);
            }
            ADD2(a0, a0, a1);
            ADD2(a2, a2, a3);
            ADD2(a0, a0, a2);
            float lo, hi;
            UNPACK2(lo, hi, a0);
            float gate = pre + lo + hi;
            act = is_tanh ? fast_tanh(gate) : fast_sigmoid(gate);
            if (!is_update) gates_s[g] = act;   // i-gates stay in 'act' register
        } else {
            // ---- warp 12: emit y(t-1) from h_s (still holds h(t-1)) — hidden under matvec ----
            if (t > 0) {
                float part = h_s[lane] * wo0 + h_s[lane + 32] * wo1 + h_s[lane + 64] * wo2;
                part += __shfl_xor_sync(0xffffffffu, part, 16);
                part += __shfl_xor_sync(0xffffffffu, part, 8);
                part += __shfl_xor_sync(0xffffffffu, part, 4);
                part += __shfl_xor_sync(0xffffffffu, part, 2);
                part += __shfl_xor_sync(0xffffffffu, part, 1);
                if (lane == 0) outrow[t - 1] = part + bo;
            }
        }
        __syncthreads();   // gates ready; warp12 done reading old h

        if (is_update) {
            // ---- phase B: c/h update (threads 0..95; i-gate activation is in 'act') ----
            float fv = gates_s[96  + g];
            float gv = gates_s[192 + g];
            float ov = gates_s[288 + g];
            c = fmaf(fv, c, act * gv);
            h_s[g] = ov * fast_tanh(c);
        }
        __syncthreads();   // h(t) visible to all
    }

    // final output y(T-1)
    if (g >= GDIM) {
        float part = h_s[lane] * wo0 + h_s[lane + 32] * wo1 + h_s[lane + 64] * wo2;
        part += __shfl_xor_sync(0xffffffffu, part, 16);
        part += __shfl_xor_sync(0xffffffffu, part, 8);
        part += __shfl_xor_sync(0xffffffffu, part, 4);
        part += __shfl_xor_sync(0xffffffffu, part, 2);
        part += __shfl_xor_sync(0xffffffffu, part, 1);
        if (lane == 0) outrow[TLEN - 1] = part + bo;
    }
}

extern "C" void kernel_launch(void* const* d_in, const int* in_sizes, int n_in,
                              void* d_out, int out_size)
{
    const float* x     = (const float*)d_in[0];
    const float* w_ih  = (const float*)d_in[1];
    const float* w_hh  = (const float*)d_in[2];
    const float* b_ih  = (const float*)d_in[3];
    const float* b_hh  = (const float*)d_in[4];
    const float* w_out = (const float*)d_in[5];
    const float* b_out = (const float*)d_in[6];
    float* out = (float*)d_out;

    lstm_persistent_kernel<<<BATCH, NTHR>>>(x, w_ih, w_hh, b_ih, b_hh,
                                            w_out, b_out, out);
}